// round 2
// baseline (speedup 1.0000x reference)
#include <cuda_runtime.h>
#include <math.h>

// Problem dims (fixed by the reference)
#define NB 8
#define LSEQ 4096
#define HID 512
#define KDIM 512
#define ODIM 1536              // 3*HID
#define MROWS (NB * LSEQ)      // 32768
#define CHUNK 128
#define NCHUNK (LSEQ / CHUNK)  // 32

// Scratch (allocation-free rule: __device__ globals)
__device__ float g_pre[(size_t)MROWS * ODIM];   // 192 MB: gate preactivations
__device__ float g_f[(size_t)MROWS * HID];      // 64 MB: forget gate f_t
__device__ float g_v[(size_t)MROWS * HID];      // 64 MB: v_t = i_t * g_t
__device__ float g_P[NCHUNK * NB * HID];        // per-chunk prod(f)
__device__ float g_Q[NCHUNK * NB * HID];        // per-chunk affine offset
__device__ float g_hs[NCHUNK * NB * HID];       // per-chunk start state

// ---------------------------------------------------------------------------
// Kernel 1: SGEMM  pre[m][o] = sum_k x[m][k] * W[o][k] + b[o]
// 128x128 tile, BK=8, 8x8 per thread, 256 threads
// ---------------------------------------------------------------------------
#define BM 128
#define BN 128
#define BK 8
#define TM 8
#define TN 8

__global__ __launch_bounds__(256)
void gemm_kernel(const float* __restrict__ A, const float* __restrict__ B,
                 const float* __restrict__ bias) {
    __shared__ float As[BK][BM];
    __shared__ float Bs[BK][BN];
    const int bx = blockIdx.x;   // o tile (0..11)
    const int by = blockIdx.y;   // m tile (0..255)
    const int tid = threadIdx.x;
    const int tcol = tid & 15;   // 0..15
    const int trow = tid >> 4;   // 0..15
    const int lrow = tid >> 1;          // 0..127
    const int lcol = (tid & 1) * 4;     // 0 or 4

    const float* Ab = A + (size_t)by * BM * KDIM;
    const float* Bb = B + (size_t)bx * BN * KDIM;

    float acc[TM][TN];
#pragma unroll
    for (int i = 0; i < TM; i++)
#pragma unroll
        for (int j = 0; j < TN; j++) acc[i][j] = 0.f;

    for (int k0 = 0; k0 < KDIM; k0 += BK) {
        float4 a4 = *(const float4*)(Ab + (size_t)lrow * KDIM + k0 + lcol);
        float4 b4 = *(const float4*)(Bb + (size_t)lrow * KDIM + k0 + lcol);
        As[lcol + 0][lrow] = a4.x; As[lcol + 1][lrow] = a4.y;
        As[lcol + 2][lrow] = a4.z; As[lcol + 3][lrow] = a4.w;
        Bs[lcol + 0][lrow] = b4.x; Bs[lcol + 1][lrow] = b4.y;
        Bs[lcol + 2][lrow] = b4.z; Bs[lcol + 3][lrow] = b4.w;
        __syncthreads();
#pragma unroll
        for (int kk = 0; kk < BK; kk++) {
            float ra[TM], rb[TN];
#pragma unroll
            for (int i = 0; i < TM; i++) ra[i] = As[kk][trow * TM + i];
#pragma unroll
            for (int j = 0; j < TN; j++) rb[j] = Bs[kk][tcol * TN + j];
#pragma unroll
            for (int i = 0; i < TM; i++)
#pragma unroll
                for (int j = 0; j < TN; j++)
                    acc[i][j] = fmaf(ra[i], rb[j], acc[i][j]);
        }
        __syncthreads();
    }

#pragma unroll
    for (int i = 0; i < TM; i++) {
        const int m = by * BM + trow * TM + i;
        const int o0 = bx * BN + tcol * TN;
        float* crow = g_pre + (size_t)m * ODIM + o0;
#pragma unroll
        for (int j = 0; j < TN; j += 4) {
            float4 v;
            v.x = acc[i][j + 0] + bias[o0 + j + 0];
            v.y = acc[i][j + 1] + bias[o0 + j + 1];
            v.z = acc[i][j + 2] + bias[o0 + j + 2];
            v.w = acc[i][j + 3] + bias[o0 + j + 3];
            *(float4*)(crow + j) = v;
        }
    }
}

// ---------------------------------------------------------------------------
// Gate math helpers
// ---------------------------------------------------------------------------
__device__ __forceinline__ float softplus_f(float z) {
    // log(1 + e^z); for z < -87 __expf underflows to 0 -> log1pf(0)=0 (correct)
    return (z > 15.f) ? z : log1pf(__expf(z));
}

// ---------------------------------------------------------------------------
// Kernel 2: per-chunk scan. Thread = (n, h, chunk).
// Computes f_t, v_t from pre; stores them; accumulates (P, Q) s.t.
//   h_end = P * h_start + Q
// ---------------------------------------------------------------------------
__global__ __launch_bounds__(128)
void scan_chunk_kernel() {
    const int h = blockIdx.x * 128 + threadIdx.x;
    const int n = blockIdx.y;
    const int c = blockIdx.z;
    const size_t m0 = (size_t)n * LSEQ + (size_t)c * CHUNK;
    const float* pre = g_pre + m0 * ODIM;
    float* fout = g_f + m0 * HID + h;
    float* vout = g_v + m0 * HID + h;

    float P = 1.f, Q = 0.f;
    for (int t = 0; t < CHUNK; t++) {
        const float fpre = pre[(size_t)t * ODIM + h];
        const float ipre = pre[(size_t)t * ODIM + HID + h];
        const float hpre = pre[(size_t)t * ODIM + 2 * HID + h];
        const float d = softplus_f(-fpre) - softplus_f(-ipre);
        const float f = 1.f / (1.f + __expf(d));       // sigmoid(-d)
        const float ig = 1.f - f;                      // sigmoid(d)
        const float g = (hpre >= 0.f) ? (hpre + 0.5f)
                                      : (1.f / (1.f + __expf(-hpre)));
        const float v = ig * g;
        fout[(size_t)t * HID] = f;
        vout[(size_t)t * HID] = v;
        P *= f;
        Q = fmaf(f, Q, v);
    }
    const int idx = c * (NB * HID) + n * HID + h;
    g_P[idx] = P;
    g_Q[idx] = Q;
}

// ---------------------------------------------------------------------------
// Kernel 3: sequential combine over chunks (tiny): per (n,h) walk 32 chunks.
// ---------------------------------------------------------------------------
__global__ __launch_bounds__(HID)
void combine_kernel() {
    const int n = blockIdx.x;
    const int h = threadIdx.x;
    float hc = 1e-6f;  // HX_INIT
    for (int c = 0; c < NCHUNK; c++) {
        const int idx = c * (NB * HID) + n * HID + h;
        g_hs[idx] = hc;
        hc = fmaf(g_P[idx], hc, g_Q[idx]);
    }
}

// ---------------------------------------------------------------------------
// Kernel 4: replay each chunk from the correct start state; write output.
// ---------------------------------------------------------------------------
__global__ __launch_bounds__(128)
void scan_write_kernel(float* __restrict__ out) {
    const int h = blockIdx.x * 128 + threadIdx.x;
    const int n = blockIdx.y;
    const int c = blockIdx.z;
    const size_t m0 = (size_t)n * LSEQ + (size_t)c * CHUNK;
    const float* fin = g_f + m0 * HID + h;
    const float* vin = g_v + m0 * HID + h;
    float* op = out + m0 * HID + h;

    float hc = g_hs[c * (NB * HID) + n * HID + h];
    for (int t = 0; t < CHUNK; t++) {
        hc = fmaf(fin[(size_t)t * HID], hc, vin[(size_t)t * HID]);
        op[(size_t)t * HID] = hc;
    }
}

// ---------------------------------------------------------------------------
extern "C" void kernel_launch(void* const* d_in, const int* in_sizes, int n_in,
                              void* d_out, int out_size) {
    const float* x = (const float*)d_in[0];  // (8, 4096, 512)
    const float* W = (const float*)d_in[1];  // (1536, 512)
    const float* b = (const float*)d_in[2];  // (1536,)
    float* out = (float*)d_out;              // (8, 4096, 512)

    dim3 gg(ODIM / BN, MROWS / BM);          // (12, 256)
    gemm_kernel<<<gg, 256>>>(x, W, b);

    dim3 gs(HID / 128, NB, NCHUNK);          // (4, 8, 32)
    scan_chunk_kernel<<<gs, 128>>>();
    combine_kernel<<<NB, HID>>>();
    scan_write_kernel<<<gs, 128>>>(out);
}

// round 5
// speedup vs baseline: 2.3878x; 2.3878x over previous
#include <cuda_runtime.h>
#include <cuda_bf16.h>
#include <cstdint>
#include <math.h>

// Problem dims (fixed by the reference)
#define NB 8
#define LSEQ 4096
#define HID 512
#define KDIM 512
#define ODIM 1536              // 3*HID
#define MROWS (NB * LSEQ)      // 32768
#define CHUNK 128
#define NCHUNK (LSEQ / CHUNK)  // 32

// Scratch (allocation-free rule: __device__ globals)
__device__ float g_pre[(size_t)MROWS * ODIM];          // 192 MB
__device__ float g_f[(size_t)MROWS * HID];             // 64 MB
__device__ float g_v[(size_t)MROWS * HID];             // 64 MB
__device__ float g_P[NCHUNK * NB * HID];
__device__ float g_Q[NCHUNK * NB * HID];
__device__ float g_hs[NCHUNK * NB * HID];
__device__ __nv_bfloat16 g_xhi[(size_t)MROWS * KDIM];  // 32 MB
__device__ __nv_bfloat16 g_xlo[(size_t)MROWS * KDIM];  // 32 MB
__device__ __nv_bfloat16 g_whi[(size_t)ODIM * KDIM];   // 1.5 MB
__device__ __nv_bfloat16 g_wlo[(size_t)ODIM * KDIM];   // 1.5 MB

// ---------------------------------------------------------------------------
// PTX helpers (baseline sm_80+ instructions only — NO tcgen05: the harness
// compiles for plain sm_103, which rejects all arch-accelerated PTX)
// ---------------------------------------------------------------------------
__device__ __forceinline__ uint32_t smem_to_u32(const void* p) {
    uint32_t a;
    asm("{ .reg .u64 t; cvta.to.shared.u64 t, %1; cvt.u32.u64 %0, t; }"
        : "=r"(a) : "l"(p));
    return a;
}

#define CP_ASYNC16(s, g) \
    asm volatile("cp.async.cg.shared.global [%0], [%1], 16;" :: "r"(s), "l"(g))
#define CP_COMMIT() asm volatile("cp.async.commit_group;" ::: "memory")
#define CP_WAIT(n)  asm volatile("cp.async.wait_group %0;" :: "n"(n) : "memory")

#define LDMX4(r0, r1, r2, r3, addr) \
    asm volatile("ldmatrix.sync.aligned.m8n8.x4.shared.b16 {%0,%1,%2,%3}, [%4];" \
                 : "=r"(r0), "=r"(r1), "=r"(r2), "=r"(r3) : "r"(addr))

#define MMA16816(d, a0, a1, a2, a3, b0, b1) \
    asm volatile("mma.sync.aligned.m16n8k16.row.col.f32.bf16.bf16.f32 " \
                 "{%0,%1,%2,%3}, {%4,%5,%6,%7}, {%8,%9}, {%0,%1,%2,%3};" \
                 : "+f"((d)[0]), "+f"((d)[1]), "+f"((d)[2]), "+f"((d)[3]) \
                 : "r"(a0), "r"(a1), "r"(a2), "r"(a3), "r"(b0), "r"(b1))

// ---------------------------------------------------------------------------
// Kernel 0: fp32 -> (bf16 hi, bf16 lo) splits
// ---------------------------------------------------------------------------
__global__ __launch_bounds__(256)
void cvt_x_kernel(const float* __restrict__ x) {
    const size_t i0 = ((size_t)blockIdx.x * 256 + threadIdx.x) * 4;
    float4 v = *(const float4*)(x + i0);
    float vv[4] = {v.x, v.y, v.z, v.w};
#pragma unroll
    for (int j = 0; j < 4; j++) {
        __nv_bfloat16 h = __float2bfloat16(vv[j]);
        g_xhi[i0 + j] = h;
        g_xlo[i0 + j] = __float2bfloat16(vv[j] - __bfloat162float(h));
    }
}

__global__ __launch_bounds__(256)
void cvt_w_kernel(const float* __restrict__ W) {
    const size_t i0 = ((size_t)blockIdx.x * 256 + threadIdx.x) * 4;
    float4 v = *(const float4*)(W + i0);
    float vv[4] = {v.x, v.y, v.z, v.w};
#pragma unroll
    for (int j = 0; j < 4; j++) {
        __nv_bfloat16 h = __float2bfloat16(vv[j]);
        g_whi[i0 + j] = h;
        g_wlo[i0 + j] = __float2bfloat16(vv[j] - __bfloat162float(h));
    }
}

// ---------------------------------------------------------------------------
// Kernel 1: bf16 mma.sync GEMM, 3-pass precision split.
//   pre[m][o] = sum_k x[m][k]*W[o][k] + b[o]
// CTA tile 128x128, 8 warps (warp tile 32x64), BK=32, 3-stage cp.async.
// Smem tiles: per stage {Ahi, Alo, Bhi, Blo}, each 128 rows x 32 bf16 (64B),
// 16B-chunk swizzle: chunk ^= (row>>1)&3  (conflict-free ldmatrix).
// ---------------------------------------------------------------------------
#define BK 32
#define NKC16 (KDIM / BK)          // 16 k-chunks
#define TILE_B (128 * BK * 2)      // 8192 bytes per tile
#define STAGE_B (4 * TILE_B)       // 32768 bytes per stage
#define NSTAGE 3
#define SM_GEMM (NSTAGE * STAGE_B) // 98304 bytes

__device__ __forceinline__ void load_stage_g(
    uint32_t sbase, int stage, int kc, int tid,
    const __nv_bfloat16* Ah, const __nv_bfloat16* Al,
    const __nv_bfloat16* Bh, const __nv_bfloat16* Bl) {
    const int k0 = kc * BK;
    const uint32_t st = sbase + stage * STAGE_B;
    const __nv_bfloat16* gsrc[4] = {Ah, Al, Bh, Bl};
#pragma unroll
    for (int tt = 0; tt < 4; tt++) {
#pragma unroll
        for (int j = 0; j < 2; j++) {
            const int idx = j * 256 + tid;      // 0..511
            const int row = idx >> 2;           // 0..127
            const int c = idx & 3;              // 16B chunk in row
            const char* g = (const char*)(gsrc[tt] + (size_t)row * KDIM + k0 + c * 8);
            const uint32_t s = st + tt * TILE_B + row * 64 +
                               ((c ^ ((row >> 1) & 3)) * 16);
            CP_ASYNC16(s, g);
        }
    }
}

__global__ __launch_bounds__(256)
void gemm_mma_kernel(const float* __restrict__ bias) {
    extern __shared__ char smem[];
    const uint32_t sbase = smem_to_u32(smem);
    const int tid = threadIdx.x;
    const int lane = tid & 31;
    const int w = tid >> 5;
    const int wm = w & 3;    // 4 M groups of 32 rows
    const int wn = w >> 2;   // 2 N groups of 64 cols
    const int bx = blockIdx.x;  // N tile (0..11)
    const int by = blockIdx.y;  // M tile (0..255)

    const __nv_bfloat16* Ah = g_xhi + (size_t)by * 128 * KDIM;
    const __nv_bfloat16* Al = g_xlo + (size_t)by * 128 * KDIM;
    const __nv_bfloat16* Bh = g_whi + (size_t)bx * 128 * KDIM;
    const __nv_bfloat16* Bl = g_wlo + (size_t)bx * 128 * KDIM;

    float acc[2][8][4];
#pragma unroll
    for (int mi = 0; mi < 2; mi++)
#pragma unroll
        for (int ni = 0; ni < 8; ni++)
#pragma unroll
            for (int r = 0; r < 4; r++) acc[mi][ni][r] = 0.f;

    // ldmatrix per-lane row/half
    const int lrow = lane & 15;
    const int lhalf = lane >> 4;

    // Prologue: stages 0,1
    load_stage_g(sbase, 0, 0, tid, Ah, Al, Bh, Bl); CP_COMMIT();
    load_stage_g(sbase, 1, 1, tid, Ah, Al, Bh, Bl); CP_COMMIT();

    for (int kc = 0; kc < NKC16; kc++) {
        if (kc == NKC16 - 1) { CP_WAIT(0); } else { CP_WAIT(1); }
        __syncthreads();
        const int stage = kc % NSTAGE;
        if (kc + 2 < NKC16) {
            load_stage_g(sbase, (kc + 2) % NSTAGE, kc + 2, tid, Ah, Al, Bh, Bl);
            CP_COMMIT();
        }

        const uint32_t st = sbase + stage * STAGE_B;
#pragma unroll
        for (int s = 0; s < 2; s++) {   // two k16 steps per BK=32
            uint32_t ahi[2][4], alo[2][4], bhi[4][4], blo[4][4];
#pragma unroll
            for (int mi = 0; mi < 2; mi++) {
                const int row = wm * 32 + mi * 16 + lrow;
                const int cS = (s * 2 + lhalf) ^ ((row >> 1) & 3);
                const uint32_t addr = st + row * 64 + cS * 16;
                LDMX4(ahi[mi][0], ahi[mi][1], ahi[mi][2], ahi[mi][3], addr);
                LDMX4(alo[mi][0], alo[mi][1], alo[mi][2], alo[mi][3], addr + TILE_B);
            }
#pragma unroll
            for (int nt = 0; nt < 4; nt++) {
                const int row = wn * 64 + nt * 16 + lrow;
                const int cS = (s * 2 + lhalf) ^ ((row >> 1) & 3);
                const uint32_t addr = st + 2 * TILE_B + row * 64 + cS * 16;
                LDMX4(bhi[nt][0], bhi[nt][1], bhi[nt][2], bhi[nt][3], addr);
                LDMX4(blo[nt][0], blo[nt][1], blo[nt][2], blo[nt][3], addr + TILE_B);
            }
            // ldmatrix x4 on a 16x16 [n][k] tile returns:
            //   r0 = n0-7  k0-7  (b0 of n-atom 0)
            //   r1 = n8-15 k0-7  (b0 of n-atom 1)
            //   r2 = n0-7  k8-15 (b1 of n-atom 0)
            //   r3 = n8-15 k8-15 (b1 of n-atom 1)
#pragma unroll
            for (int mi = 0; mi < 2; mi++)
#pragma unroll
                for (int nt = 0; nt < 4; nt++)
#pragma unroll
                    for (int a = 0; a < 2; a++) {
                        const int ni = nt * 2 + a;
                        // pass 1: hi*hi
                        MMA16816(acc[mi][ni], ahi[mi][0], ahi[mi][1], ahi[mi][2],
                                 ahi[mi][3], bhi[nt][a], bhi[nt][a + 2]);
                        // pass 2: lo*hi
                        MMA16816(acc[mi][ni], alo[mi][0], alo[mi][1], alo[mi][2],
                                 alo[mi][3], bhi[nt][a], bhi[nt][a + 2]);
                        // pass 3: hi*lo
                        MMA16816(acc[mi][ni], ahi[mi][0], ahi[mi][1], ahi[mi][2],
                                 ahi[mi][3], blo[nt][a], blo[nt][a + 2]);
                    }
        }
    }

    // Epilogue: add bias, write fp32 pre
#pragma unroll
    for (int mi = 0; mi < 2; mi++) {
        const int row = by * 128 + wm * 32 + mi * 16 + (lane >> 2);
#pragma unroll
        for (int ni = 0; ni < 8; ni++) {
            const int col = bx * 128 + wn * 64 + ni * 8 + (lane & 3) * 2;
            const float b0 = bias[col], b1 = bias[col + 1];
            float2 v0 = make_float2(acc[mi][ni][0] + b0, acc[mi][ni][1] + b1);
            float2 v1 = make_float2(acc[mi][ni][2] + b0, acc[mi][ni][3] + b1);
            *(float2*)(g_pre + (size_t)row * ODIM + col) = v0;
            *(float2*)(g_pre + (size_t)(row + 8) * ODIM + col) = v1;
        }
    }
}

// ---------------------------------------------------------------------------
// Gate math helpers
// ---------------------------------------------------------------------------
__device__ __forceinline__ float softplus_f(float z) {
    return (z > 15.f) ? z : log1pf(__expf(z));
}

// ---------------------------------------------------------------------------
// Kernel 2: per-chunk scan: compute gates, store (f, v), chunk (P, Q).
// ---------------------------------------------------------------------------
__global__ __launch_bounds__(128)
void scan_chunk_kernel() {
    const int h = blockIdx.x * 128 + threadIdx.x;
    const int n = blockIdx.y;
    const int c = blockIdx.z;
    const size_t m0 = (size_t)n * LSEQ + (size_t)c * CHUNK;
    const float* pre = g_pre + m0 * ODIM;
    float* fout = g_f + m0 * HID + h;
    float* vout = g_v + m0 * HID + h;

    float P = 1.f, Q = 0.f;
    for (int t = 0; t < CHUNK; t++) {
        const float fpre = pre[(size_t)t * ODIM + h];
        const float ipre = pre[(size_t)t * ODIM + HID + h];
        const float hpre = pre[(size_t)t * ODIM + 2 * HID + h];
        const float d = softplus_f(-fpre) - softplus_f(-ipre);
        const float f = 1.f / (1.f + __expf(d));
        const float ig = 1.f - f;
        const float g = (hpre >= 0.f) ? (hpre + 0.5f)
                                      : (1.f / (1.f + __expf(-hpre)));
        const float v = ig * g;
        fout[(size_t)t * HID] = f;
        vout[(size_t)t * HID] = v;
        P *= f;
        Q = fmaf(f, Q, v);
    }
    const int idx = c * (NB * HID) + n * HID + h;
    g_P[idx] = P;
    g_Q[idx] = Q;
}

// ---------------------------------------------------------------------------
// Kernel 3: sequential combine over chunks.
// ---------------------------------------------------------------------------
__global__ __launch_bounds__(HID)
void combine_kernel() {
    const int n = blockIdx.x;
    const int h = threadIdx.x;
    float hc = 1e-6f;  // HX_INIT
    for (int c = 0; c < NCHUNK; c++) {
        const int idx = c * (NB * HID) + n * HID + h;
        g_hs[idx] = hc;
        hc = fmaf(g_P[idx], hc, g_Q[idx]);
    }
}

// ---------------------------------------------------------------------------
// Kernel 4: replay each chunk from its start state; write output.
// ---------------------------------------------------------------------------
__global__ __launch_bounds__(128)
void scan_write_kernel(float* __restrict__ out) {
    const int h = blockIdx.x * 128 + threadIdx.x;
    const int n = blockIdx.y;
    const int c = blockIdx.z;
    const size_t m0 = (size_t)n * LSEQ + (size_t)c * CHUNK;
    const float* fin = g_f + m0 * HID + h;
    const float* vin = g_v + m0 * HID + h;
    float* op = out + m0 * HID + h;

    float hc = g_hs[c * (NB * HID) + n * HID + h];
    for (int t = 0; t < CHUNK; t++) {
        hc = fmaf(fin[(size_t)t * HID], hc, vin[(size_t)t * HID]);
        op[(size_t)t * HID] = hc;
    }
}

// ---------------------------------------------------------------------------
extern "C" void kernel_launch(void* const* d_in, const int* in_sizes, int n_in,
                              void* d_out, int out_size) {
    const float* x = (const float*)d_in[0];  // (8, 4096, 512)
    const float* W = (const float*)d_in[1];  // (1536, 512)
    const float* b = (const float*)d_in[2];  // (1536,)
    float* out = (float*)d_out;              // (8, 4096, 512)

    cudaFuncSetAttribute(gemm_mma_kernel,
                         cudaFuncAttributeMaxDynamicSharedMemorySize, SM_GEMM);

    cvt_x_kernel<<<(MROWS * KDIM) / (256 * 4), 256>>>(x);
    cvt_w_kernel<<<(ODIM * KDIM) / (256 * 4), 256>>>(W);

    dim3 gg(ODIM / 128, MROWS / 128);        // (12, 256)
    gemm_mma_kernel<<<gg, 256, SM_GEMM>>>(b);

    dim3 gs(HID / 128, NB, NCHUNK);          // (4, 8, 32)
    scan_chunk_kernel<<<gs, 128>>>();
    combine_kernel<<<NB, HID>>>();
    scan_write_kernel<<<gs, 128>>>(out);
}

// round 6
// speedup vs baseline: 3.1772x; 1.3306x over previous
#include <cuda_runtime.h>
#include <cuda_fp16.h>
#include <cstdint>
#include <math.h>

// Problem dims (fixed by the reference)
#define NB 8
#define LSEQ 4096
#define HID 512
#define KDIM 512
#define ODIM 1536              // 3*HID
#define MROWS (NB * LSEQ)      // 32768
#define CHUNK 64
#define NCHUNK (LSEQ / CHUNK)  // 64

// Scratch (allocation-free rule: __device__ globals)
__device__ float g_pre[(size_t)MROWS * ODIM];      // 192 MB
__device__ float g_f[(size_t)MROWS * HID];         // 64 MB
__device__ float g_v[(size_t)MROWS * HID];         // 64 MB
__device__ float g_P[NCHUNK * NB * HID];
__device__ float g_Q[NCHUNK * NB * HID];
__device__ float g_hs[NCHUNK * NB * HID];
__device__ __half g_xhi[(size_t)MROWS * KDIM];     // 32 MB
__device__ __half g_xlo[(size_t)MROWS * KDIM];     // 32 MB
__device__ __half g_whi[(size_t)ODIM * KDIM];      // 1.5 MB

// ---------------------------------------------------------------------------
// PTX helpers (baseline sm_80+ only — plain sm_103 target rejects tcgen05)
// ---------------------------------------------------------------------------
__device__ __forceinline__ uint32_t smem_to_u32(const void* p) {
    uint32_t a;
    asm("{ .reg .u64 t; cvta.to.shared.u64 t, %1; cvt.u32.u64 %0, t; }"
        : "=r"(a) : "l"(p));
    return a;
}

#define CP_ASYNC16(s, g) \
    asm volatile("cp.async.cg.shared.global [%0], [%1], 16;" :: "r"(s), "l"(g))
#define CP_COMMIT() asm volatile("cp.async.commit_group;" ::: "memory")
#define CP_WAIT(n)  asm volatile("cp.async.wait_group %0;" :: "n"(n) : "memory")

#define LDMX4(r0, r1, r2, r3, addr) \
    asm volatile("ldmatrix.sync.aligned.m8n8.x4.shared.b16 {%0,%1,%2,%3}, [%4];" \
                 : "=r"(r0), "=r"(r1), "=r"(r2), "=r"(r3) : "r"(addr))

#define MMA16816(d, a0, a1, a2, a3, b0, b1) \
    asm volatile("mma.sync.aligned.m16n8k16.row.col.f32.f16.f16.f32 " \
                 "{%0,%1,%2,%3}, {%4,%5,%6,%7}, {%8,%9}, {%0,%1,%2,%3};" \
                 : "+f"((d)[0]), "+f"((d)[1]), "+f"((d)[2]), "+f"((d)[3]) \
                 : "r"(a0), "r"(a1), "r"(a2), "r"(a3), "r"(b0), "r"(b1))

// ---------------------------------------------------------------------------
// Kernel 0: fp32 -> fp16 splits. x -> (hi, lo); W -> hi only (the dropped
// x*W_lo cross term is ~2^-12 relative on pre — inside tolerance).
// ---------------------------------------------------------------------------
__global__ __launch_bounds__(256)
void cvt_x_kernel(const float* __restrict__ x) {
    const size_t i0 = ((size_t)blockIdx.x * 256 + threadIdx.x) * 4;
    float4 v = *(const float4*)(x + i0);
    float vv[4] = {v.x, v.y, v.z, v.w};
#pragma unroll
    for (int j = 0; j < 4; j++) {
        __half h = __float2half(vv[j]);
        g_xhi[i0 + j] = h;
        g_xlo[i0 + j] = __float2half(vv[j] - __half2float(h));
    }
}

__global__ __launch_bounds__(256)
void cvt_w_kernel(const float* __restrict__ W) {
    const size_t i0 = ((size_t)blockIdx.x * 256 + threadIdx.x) * 4;
    float4 v = *(const float4*)(W + i0);
    float vv[4] = {v.x, v.y, v.z, v.w};
#pragma unroll
    for (int j = 0; j < 4; j++) g_whi[i0 + j] = __float2half(vv[j]);
}

// ---------------------------------------------------------------------------
// Kernel 1: fp16 mma.sync GEMM, 2-pass precision split.
//   pre[m][o] = (x_hi + x_lo)[m][k] * W_hi[o][k] + b[o]
// CTA tile 128x128, 8 warps (warp tile 32x64), BK=32, 3-stage cp.async.
// Smem per stage: {Ahi, Alo, Bhi}, each 128 rows x 32 fp16 (64B/row),
// 16B-chunk swizzle: chunk ^= (row>>1)&3 (conflict-free ldmatrix).
// ---------------------------------------------------------------------------
#define BK 32
#define NKC16 (KDIM / BK)          // 16 k-chunks
#define TILE_B (128 * BK * 2)      // 8192 bytes per tile
#define STAGE_B (3 * TILE_B)       // 24576 bytes per stage
#define NSTAGE 3
#define SM_GEMM (NSTAGE * STAGE_B) // 73728 bytes

__device__ __forceinline__ void load_stage_g(
    uint32_t sbase, int stage, int kc, int tid,
    const __half* Ah, const __half* Al, const __half* Bh) {
    const int k0 = kc * BK;
    const uint32_t st = sbase + stage * STAGE_B;
    const __half* gsrc[3] = {Ah, Al, Bh};
#pragma unroll
    for (int tt = 0; tt < 3; tt++) {
#pragma unroll
        for (int j = 0; j < 2; j++) {
            const int idx = j * 256 + tid;      // 0..511
            const int row = idx >> 2;           // 0..127
            const int c = idx & 3;              // 16B chunk in row
            const char* g = (const char*)(gsrc[tt] + (size_t)row * KDIM + k0 + c * 8);
            const uint32_t s = st + tt * TILE_B + row * 64 +
                               ((c ^ ((row >> 1) & 3)) * 16);
            CP_ASYNC16(s, g);
        }
    }
}

__global__ __launch_bounds__(256)
void gemm_mma_kernel(const float* __restrict__ bias) {
    extern __shared__ char smem[];
    const uint32_t sbase = smem_to_u32(smem);
    const int tid = threadIdx.x;
    const int lane = tid & 31;
    const int w = tid >> 5;
    const int wm = w & 3;    // 4 M groups of 32 rows
    const int wn = w >> 2;   // 2 N groups of 64 cols
    const int bx = blockIdx.x;  // N tile (0..11)
    const int by = blockIdx.y;  // M tile (0..255)

    const __half* Ah = g_xhi + (size_t)by * 128 * KDIM;
    const __half* Al = g_xlo + (size_t)by * 128 * KDIM;
    const __half* Bh = g_whi + (size_t)bx * 128 * KDIM;

    float acc[2][8][4];
#pragma unroll
    for (int mi = 0; mi < 2; mi++)
#pragma unroll
        for (int ni = 0; ni < 8; ni++)
#pragma unroll
            for (int r = 0; r < 4; r++) acc[mi][ni][r] = 0.f;

    const int lrow = lane & 15;
    const int lhalf = lane >> 4;

    load_stage_g(sbase, 0, 0, tid, Ah, Al, Bh); CP_COMMIT();
    load_stage_g(sbase, 1, 1, tid, Ah, Al, Bh); CP_COMMIT();

    for (int kc = 0; kc < NKC16; kc++) {
        if (kc == NKC16 - 1) { CP_WAIT(0); } else { CP_WAIT(1); }
        __syncthreads();
        const int stage = kc % NSTAGE;
        if (kc + 2 < NKC16) {
            load_stage_g(sbase, (kc + 2) % NSTAGE, kc + 2, tid, Ah, Al, Bh);
            CP_COMMIT();
        }

        const uint32_t st = sbase + stage * STAGE_B;
#pragma unroll
        for (int s = 0; s < 2; s++) {   // two k16 steps per BK=32
            uint32_t ahi[2][4], alo[2][4], bhi[4][4];
#pragma unroll
            for (int mi = 0; mi < 2; mi++) {
                const int row = wm * 32 + mi * 16 + lrow;
                const int cS = (s * 2 + lhalf) ^ ((row >> 1) & 3);
                const uint32_t addr = st + row * 64 + cS * 16;
                LDMX4(ahi[mi][0], ahi[mi][1], ahi[mi][2], ahi[mi][3], addr);
                LDMX4(alo[mi][0], alo[mi][1], alo[mi][2], alo[mi][3], addr + TILE_B);
            }
#pragma unroll
            for (int nt = 0; nt < 4; nt++) {
                const int row = wn * 64 + nt * 16 + lrow;
                const int cS = (s * 2 + lhalf) ^ ((row >> 1) & 3);
                const uint32_t addr = st + 2 * TILE_B + row * 64 + cS * 16;
                LDMX4(bhi[nt][0], bhi[nt][1], bhi[nt][2], bhi[nt][3], addr);
            }
#pragma unroll
            for (int mi = 0; mi < 2; mi++)
#pragma unroll
                for (int nt = 0; nt < 4; nt++)
#pragma unroll
                    for (int a = 0; a < 2; a++) {
                        const int ni = nt * 2 + a;
                        MMA16816(acc[mi][ni], ahi[mi][0], ahi[mi][1], ahi[mi][2],
                                 ahi[mi][3], bhi[nt][a], bhi[nt][a + 2]);
                        MMA16816(acc[mi][ni], alo[mi][0], alo[mi][1], alo[mi][2],
                                 alo[mi][3], bhi[nt][a], bhi[nt][a + 2]);
                    }
        }
    }

    // Epilogue: add bias, write fp32 pre
#pragma unroll
    for (int mi = 0; mi < 2; mi++) {
        const int row = by * 128 + wm * 32 + mi * 16 + (lane >> 2);
#pragma unroll
        for (int ni = 0; ni < 8; ni++) {
            const int col = bx * 128 + wn * 64 + ni * 8 + (lane & 3) * 2;
            const float b0 = bias[col], b1 = bias[col + 1];
            float2 v0 = make_float2(acc[mi][ni][0] + b0, acc[mi][ni][1] + b1);
            float2 v1 = make_float2(acc[mi][ni][2] + b0, acc[mi][ni][3] + b1);
            *(float2*)(g_pre + (size_t)row * ODIM + col) = v0;
            *(float2*)(g_pre + (size_t)(row + 8) * ODIM + col) = v1;
        }
    }
}

// ---------------------------------------------------------------------------
// Gate math (closed form, no softplus):
//   f  = sigmoid(softplus(-i_pre) - softplus(-f_pre))
//      = (1+e^{-ip}) / (2 + e^{-fp} + e^{-ip});   i = 1 - f
//   g  = hp>=0 ? hp+0.5 : sigmoid(hp)
// ---------------------------------------------------------------------------
__device__ __forceinline__ void gates(float fp, float ip, float hp,
                                      float& f, float& v) {
    const float a = __expf(-fp);
    const float b = __expf(-ip);
    f = __fdividef(1.f + b, 2.f + a + b);
    const float ig = 1.f - f;
    const float gg = (hp >= 0.f) ? (hp + 0.5f)
                                 : __fdividef(1.f, 1.f + __expf(-hp));
    v = ig * gg;
}

// ---------------------------------------------------------------------------
// Kernel 2: per-chunk scan (2 h per thread, float2): compute gates,
// store (f, v), accumulate chunk (P, Q) s.t. h_end = P*h_start + Q.
// ---------------------------------------------------------------------------
__global__ __launch_bounds__(128)
void scan_chunk_kernel() {
    const int h2 = (blockIdx.x * 128 + threadIdx.x) * 2;
    const int n = blockIdx.y;
    const int c = blockIdx.z;
    const size_t m0 = (size_t)n * LSEQ + (size_t)c * CHUNK;
    const float* pre = g_pre + m0 * ODIM;

    float2 P = make_float2(1.f, 1.f), Q = make_float2(0.f, 0.f);
#pragma unroll 4
    for (int t = 0; t < CHUNK; t++) {
        const float2 fp = *(const float2*)(pre + (size_t)t * ODIM + h2);
        const float2 ip = *(const float2*)(pre + (size_t)t * ODIM + HID + h2);
        const float2 hp = *(const float2*)(pre + (size_t)t * ODIM + 2 * HID + h2);
        float2 f, v;
        gates(fp.x, ip.x, hp.x, f.x, v.x);
        gates(fp.y, ip.y, hp.y, f.y, v.y);
        *(float2*)(g_f + (m0 + t) * HID + h2) = f;
        *(float2*)(g_v + (m0 + t) * HID + h2) = v;
        P.x *= f.x; P.y *= f.y;
        Q.x = fmaf(f.x, Q.x, v.x);
        Q.y = fmaf(f.y, Q.y, v.y);
    }
    const int idx = c * (NB * HID) + n * HID + h2;
    *(float2*)(g_P + idx) = P;
    *(float2*)(g_Q + idx) = Q;
}

// ---------------------------------------------------------------------------
// Kernel 3: sequential combine over chunks (tiny).
// ---------------------------------------------------------------------------
__global__ __launch_bounds__(HID)
void combine_kernel() {
    const int n = blockIdx.x;
    const int h = threadIdx.x;
    float hc = 1e-6f;  // HX_INIT
    for (int c = 0; c < NCHUNK; c++) {
        const int idx = c * (NB * HID) + n * HID + h;
        g_hs[idx] = hc;
        hc = fmaf(g_P[idx], hc, g_Q[idx]);
    }
}

// ---------------------------------------------------------------------------
// Kernel 4: replay each chunk from its start state; write output.
// ---------------------------------------------------------------------------
__global__ __launch_bounds__(128)
void scan_write_kernel(float* __restrict__ out) {
    const int h2 = (blockIdx.x * 128 + threadIdx.x) * 2;
    const int n = blockIdx.y;
    const int c = blockIdx.z;
    const size_t m0 = (size_t)n * LSEQ + (size_t)c * CHUNK;
    const float* fin = g_f + m0 * HID + h2;
    const float* vin = g_v + m0 * HID + h2;
    float* op = out + m0 * HID + h2;

    float2 hc = *(const float2*)(g_hs + c * (NB * HID) + n * HID + h2);
#pragma unroll 4
    for (int t = 0; t < CHUNK; t++) {
        const float2 f = *(const float2*)(fin + (size_t)t * HID);
        const float2 v = *(const float2*)(vin + (size_t)t * HID);
        hc.x = fmaf(f.x, hc.x, v.x);
        hc.y = fmaf(f.y, hc.y, v.y);
        *(float2*)(op + (size_t)t * HID) = hc;
    }
}

// ---------------------------------------------------------------------------
extern "C" void kernel_launch(void* const* d_in, const int* in_sizes, int n_in,
                              void* d_out, int out_size) {
    const float* x = (const float*)d_in[0];  // (8, 4096, 512)
    const float* W = (const float*)d_in[1];  // (1536, 512)
    const float* b = (const float*)d_in[2];  // (1536,)
    float* out = (float*)d_out;              // (8, 4096, 512)

    cudaFuncSetAttribute(gemm_mma_kernel,
                         cudaFuncAttributeMaxDynamicSharedMemorySize, SM_GEMM);

    cvt_x_kernel<<<(MROWS * KDIM) / (256 * 4), 256>>>(x);
    cvt_w_kernel<<<(ODIM * KDIM) / (256 * 4), 256>>>(W);

    dim3 gg(ODIM / 128, MROWS / 128);        // (12, 256)
    gemm_mma_kernel<<<gg, 256, SM_GEMM>>>(b);

    dim3 gs(HID / 256, NB, NCHUNK);          // (2, 8, 64)
    scan_chunk_kernel<<<gs, 128>>>();
    combine_kernel<<<NB, HID>>>();
    scan_write_kernel<<<gs, 128>>>(out);
}

// round 9
// speedup vs baseline: 4.7866x; 1.5065x over previous
#include <cuda_runtime.h>
#include <cuda_fp16.h>
#include <cstdint>
#include <math.h>

// Problem dims (fixed by the reference)
#define NB 8
#define LSEQ 4096
#define HID 512
#define KDIM 512
#define ODIM 1536              // 3*HID
#define MROWS (NB * LSEQ)      // 32768
#define CHUNK 64
#define NCHUNK (LSEQ / CHUNK)  // 64

// Scratch (allocation-free rule: __device__ globals)
__device__ float g_pre[(size_t)MROWS * ODIM];      // 192 MB
__device__ float g_f[(size_t)MROWS * HID];         // 64 MB
__device__ float g_v[(size_t)MROWS * HID];         // 64 MB
__device__ float g_P[NCHUNK * NB * HID];
__device__ float g_Q[NCHUNK * NB * HID];
__device__ float g_hs[NCHUNK * NB * HID];
__device__ __half g_xhi[(size_t)MROWS * KDIM];     // 32 MB
__device__ __half g_whi[(size_t)ODIM * KDIM];      // 1.5 MB

// ---------------------------------------------------------------------------
// PTX helpers (baseline sm_80+ only — plain sm_103 target rejects tcgen05)
// ---------------------------------------------------------------------------
__device__ __forceinline__ uint32_t smem_to_u32(const void* p) {
    uint32_t a;
    asm("{ .reg .u64 t; cvta.to.shared.u64 t, %1; cvt.u32.u64 %0, t; }"
        : "=r"(a) : "l"(p));
    return a;
}

#define CP_ASYNC16(s, g) \
    asm volatile("cp.async.cg.shared.global [%0], [%1], 16;" :: "r"(s), "l"(g))
#define CP_COMMIT() asm volatile("cp.async.commit_group;" ::: "memory")
#define CP_WAIT(n)  asm volatile("cp.async.wait_group %0;" :: "n"(n) : "memory")

#define LDMX4(r0, r1, r2, r3, addr) \
    asm volatile("ldmatrix.sync.aligned.m8n8.x4.shared.b16 {%0,%1,%2,%3}, [%4];" \
                 : "=r"(r0), "=r"(r1), "=r"(r2), "=r"(r3) : "r"(addr))

#define MMA16816(d, a0, a1, a2, a3, b0, b1) \
    asm volatile("mma.sync.aligned.m16n8k16.row.col.f32.f16.f16.f32 " \
                 "{%0,%1,%2,%3}, {%4,%5,%6,%7}, {%8,%9}, {%0,%1,%2,%3};" \
                 : "+f"((d)[0]), "+f"((d)[1]), "+f"((d)[2]), "+f"((d)[3]) \
                 : "r"(a0), "r"(a1), "r"(a2), "r"(a3), "r"(b0), "r"(b1))

// ---------------------------------------------------------------------------
// Kernel 0: fp32 -> fp16 (single precision pass: measured error budget from
// rounds 4/5 shows each dropped fp16 cross term costs ~1e-4 rel_err;
// 1-pass lands ~3e-4, safely under the 1e-3 gate).
// ---------------------------------------------------------------------------
__global__ __launch_bounds__(256)
void cvt_x_kernel(const float* __restrict__ x) {
    const size_t i0 = ((size_t)blockIdx.x * 256 + threadIdx.x) * 4;
    float4 v = *(const float4*)(x + i0);
    __half2 h01 = __floats2half2_rn(v.x, v.y);
    __half2 h23 = __floats2half2_rn(v.z, v.w);
    *(__half2*)(g_xhi + i0) = h01;
    *(__half2*)(g_xhi + i0 + 2) = h23;
}

__global__ __launch_bounds__(256)
void cvt_w_kernel(const float* __restrict__ W) {
    const size_t i0 = ((size_t)blockIdx.x * 256 + threadIdx.x) * 4;
    float4 v = *(const float4*)(W + i0);
    __half2 h01 = __floats2half2_rn(v.x, v.y);
    __half2 h23 = __floats2half2_rn(v.z, v.w);
    *(__half2*)(g_whi + i0) = h01;
    *(__half2*)(g_whi + i0 + 2) = h23;
}

// ---------------------------------------------------------------------------
// Kernel 1: fp16 mma.sync GEMM, single pass.
//   pre[m][o] = x[m][k] * W[o][k] + b[o]
// CTA tile 128x128, 8 warps (warp tile 32x64), BK=64, 3-stage cp.async.
// Smem per stage: {A, B}, each 128 rows x 64 fp16 (128B/row),
// swizzle: 16B-chunk c ^= (row & 7) — conflict-free for cp.async + ldmatrix.
// ---------------------------------------------------------------------------
#define BK 64
#define NKC (KDIM / BK)            // 8 k-chunks
#define TILE_B (128 * BK * 2)      // 16384 bytes per tile
#define STAGE_B (2 * TILE_B)       // 32768 bytes per stage
#define NSTAGE 3
#define SM_GEMM (NSTAGE * STAGE_B) // 98304 bytes

__device__ __forceinline__ void load_stage_g(
    uint32_t sbase, int stage, int kc, int tid,
    const __half* Ah, const __half* Bh) {
    const int k0 = kc * BK;
    const uint32_t st = sbase + stage * STAGE_B;
    const __half* gsrc[2] = {Ah, Bh};
#pragma unroll
    for (int tt = 0; tt < 2; tt++) {
#pragma unroll
        for (int j = 0; j < 4; j++) {
            const int idx = j * 256 + tid;      // 0..1023
            const int row = idx >> 3;           // 0..127
            const int c = idx & 7;              // 16B chunk in 128B row
            const char* g = (const char*)(gsrc[tt] + (size_t)row * KDIM + k0 + c * 8);
            const uint32_t s = st + tt * TILE_B + row * 128 +
                               ((c ^ (row & 7)) * 16);
            CP_ASYNC16(s, g);
        }
    }
}

__global__ __launch_bounds__(256)
void gemm_mma_kernel(const float* __restrict__ bias) {
    extern __shared__ char smem[];
    const uint32_t sbase = smem_to_u32(smem);
    const int tid = threadIdx.x;
    const int lane = tid & 31;
    const int w = tid >> 5;
    const int wm = w & 3;    // 4 M groups of 32 rows
    const int wn = w >> 2;   // 2 N groups of 64 cols
    const int bx = blockIdx.x;  // N tile (0..11)
    const int by = blockIdx.y;  // M tile (0..255)

    const __half* Ah = g_xhi + (size_t)by * 128 * KDIM;
    const __half* Bh = g_whi + (size_t)bx * 128 * KDIM;

    float acc[2][8][4];
#pragma unroll
    for (int mi = 0; mi < 2; mi++)
#pragma unroll
        for (int ni = 0; ni < 8; ni++)
#pragma unroll
            for (int r = 0; r < 4; r++) acc[mi][ni][r] = 0.f;

    const int lrow = lane & 15;
    const int lhalf = lane >> 4;

    load_stage_g(sbase, 0, 0, tid, Ah, Bh); CP_COMMIT();
    load_stage_g(sbase, 1, 1, tid, Ah, Bh); CP_COMMIT();

    for (int kc = 0; kc < NKC; kc++) {
        if (kc == NKC - 1) { CP_WAIT(0); } else { CP_WAIT(1); }
        __syncthreads();
        const int stage = kc % NSTAGE;
        if (kc + 2 < NKC) {
            load_stage_g(sbase, (kc + 2) % NSTAGE, kc + 2, tid, Ah, Bh);
            CP_COMMIT();
        }

        const uint32_t st = sbase + stage * STAGE_B;
#pragma unroll
        for (int s = 0; s < 4; s++) {   // four k16 steps per BK=64
            uint32_t af[2][4], bf[4][4];
#pragma unroll
            for (int mi = 0; mi < 2; mi++) {
                const int row = wm * 32 + mi * 16 + lrow;
                const int cS = (s * 2 + lhalf) ^ (row & 7);
                LDMX4(af[mi][0], af[mi][1], af[mi][2], af[mi][3],
                      st + row * 128 + cS * 16);
            }
#pragma unroll
            for (int nt = 0; nt < 4; nt++) {
                const int row = wn * 64 + nt * 16 + lrow;
                const int cS = (s * 2 + lhalf) ^ (row & 7);
                LDMX4(bf[nt][0], bf[nt][1], bf[nt][2], bf[nt][3],
                      st + TILE_B + row * 128 + cS * 16);
            }
            // ldmatrix x4 on 16x16 [n][k]: r0=n0-7 k0-7, r1=n8-15 k0-7,
            //                              r2=n0-7 k8-15, r3=n8-15 k8-15
#pragma unroll
            for (int mi = 0; mi < 2; mi++)
#pragma unroll
                for (int nt = 0; nt < 4; nt++)
#pragma unroll
                    for (int a = 0; a < 2; a++) {
                        const int ni = nt * 2 + a;
                        MMA16816(acc[mi][ni], af[mi][0], af[mi][1], af[mi][2],
                                 af[mi][3], bf[nt][a], bf[nt][a + 2]);
                    }
        }
    }

    // Epilogue: add bias, write fp32 pre
#pragma unroll
    for (int mi = 0; mi < 2; mi++) {
        const int row = by * 128 + wm * 32 + mi * 16 + (lane >> 2);
#pragma unroll
        for (int ni = 0; ni < 8; ni++) {
            const int col = bx * 128 + wn * 64 + ni * 8 + (lane & 3) * 2;
            const float b0 = bias[col], b1 = bias[col + 1];
            float2 v0 = make_float2(acc[mi][ni][0] + b0, acc[mi][ni][1] + b1);
            float2 v1 = make_float2(acc[mi][ni][2] + b0, acc[mi][ni][3] + b1);
            *(float2*)(g_pre + (size_t)row * ODIM + col) = v0;
            *(float2*)(g_pre + (size_t)(row + 8) * ODIM + col) = v1;
        }
    }
}

// ---------------------------------------------------------------------------
// Gate math (closed form, no softplus):
//   f = (1+e^{-ip}) / (2 + e^{-fp} + e^{-ip});   i = 1 - f
//   g = hp>=0 ? hp+0.5 : sigmoid(hp)
// ---------------------------------------------------------------------------
__device__ __forceinline__ void gates(float fp, float ip, float hp,
                                      float& f, float& v) {
    const float a = __expf(-fp);
    const float b = __expf(-ip);
    f = __fdividef(1.f + b, 2.f + a + b);
    const float ig = 1.f - f;
    const float gg = (hp >= 0.f) ? (hp + 0.5f)
                                 : __fdividef(1.f, 1.f + __expf(-hp));
    v = ig * gg;
}

// ---------------------------------------------------------------------------
// Kernel 2: per-chunk scan (4 h per thread, float4): compute gates,
// store (f, v), accumulate chunk (P, Q) s.t. h_end = P*h_start + Q.
// ---------------------------------------------------------------------------
__global__ __launch_bounds__(128)
void scan_chunk_kernel() {
    const int h4 = (blockIdx.x * 128 + threadIdx.x) * 4;
    const int n = blockIdx.y;
    const int c = blockIdx.z;
    const size_t m0 = (size_t)n * LSEQ + (size_t)c * CHUNK;
    const float* pre = g_pre + m0 * ODIM;

    float4 P = make_float4(1.f, 1.f, 1.f, 1.f);
    float4 Q = make_float4(0.f, 0.f, 0.f, 0.f);
#pragma unroll 2
    for (int t = 0; t < CHUNK; t++) {
        const float4 fp = *(const float4*)(pre + (size_t)t * ODIM + h4);
        const float4 ip = *(const float4*)(pre + (size_t)t * ODIM + HID + h4);
        const float4 hp = *(const float4*)(pre + (size_t)t * ODIM + 2 * HID + h4);
        float4 f, v;
        gates(fp.x, ip.x, hp.x, f.x, v.x);
        gates(fp.y, ip.y, hp.y, f.y, v.y);
        gates(fp.z, ip.z, hp.z, f.z, v.z);
        gates(fp.w, ip.w, hp.w, f.w, v.w);
        *(float4*)(g_f + (m0 + t) * HID + h4) = f;
        *(float4*)(g_v + (m0 + t) * HID + h4) = v;
        P.x *= f.x; P.y *= f.y; P.z *= f.z; P.w *= f.w;
        Q.x = fmaf(f.x, Q.x, v.x);
        Q.y = fmaf(f.y, Q.y, v.y);
        Q.z = fmaf(f.z, Q.z, v.z);
        Q.w = fmaf(f.w, Q.w, v.w);
    }
    const int idx = c * (NB * HID) + n * HID + h4;
    *(float4*)(g_P + idx) = P;
    *(float4*)(g_Q + idx) = Q;
}

// ---------------------------------------------------------------------------
// Kernel 3: sequential combine over chunks (tiny).
// ---------------------------------------------------------------------------
__global__ __launch_bounds__(HID)
void combine_kernel() {
    const int n = blockIdx.x;
    const int h = threadIdx.x;
    float hc = 1e-6f;  // HX_INIT
    for (int c = 0; c < NCHUNK; c++) {
        const int idx = c * (NB * HID) + n * HID + h;
        g_hs[idx] = hc;
        hc = fmaf(g_P[idx], hc, g_Q[idx]);
    }
}

// ---------------------------------------------------------------------------
// Kernel 4: replay each chunk from its start state; write output.
// ---------------------------------------------------------------------------
__global__ __launch_bounds__(128)
void scan_write_kernel(float* __restrict__ out) {
    const int h4 = (blockIdx.x * 128 + threadIdx.x) * 4;
    const int n = blockIdx.y;
    const int c = blockIdx.z;
    const size_t m0 = (size_t)n * LSEQ + (size_t)c * CHUNK;
    const float* fin = g_f + m0 * HID + h4;
    const float* vin = g_v + m0 * HID + h4;
    float* op = out + m0 * HID + h4;

    float4 hc = *(const float4*)(g_hs + c * (NB * HID) + n * HID + h4);
#pragma unroll 2
    for (int t = 0; t < CHUNK; t++) {
        const float4 f = *(const float4*)(fin + (size_t)t * HID);
        const float4 v = *(const float4*)(vin + (size_t)t * HID);
        hc.x = fmaf(f.x, hc.x, v.x);
        hc.y = fmaf(f.y, hc.y, v.y);
        hc.z = fmaf(f.z, hc.z, v.z);
        hc.w = fmaf(f.w, hc.w, v.w);
        *(float4*)(op + (size_t)t * HID) = hc;
    }
}

// ---------------------------------------------------------------------------
extern "C" void kernel_launch(void* const* d_in, const int* in_sizes, int n_in,
                              void* d_out, int out_size) {
    const float* x = (const float*)d_in[0];  // (8, 4096, 512)
    const float* W = (const float*)d_in[1];  // (1536, 512)
    const float* b = (const float*)d_in[2];  // (1536,)
    float* out = (float*)d_out;              // (8, 4096, 512)

    cudaFuncSetAttribute(gemm_mma_kernel,
                         cudaFuncAttributeMaxDynamicSharedMemorySize, SM_GEMM);

    cvt_x_kernel<<<(MROWS * KDIM) / (256 * 4), 256>>>(x);
    cvt_w_kernel<<<(ODIM * KDIM) / (256 * 4), 256>>>(W);

    dim3 gg(ODIM / 128, MROWS / 128);        // (12, 256)
    gemm_mma_kernel<<<gg, 256, SM_GEMM>>>(b);

    dim3 gs(HID / 512, NB, NCHUNK);          // (1, 8, 64)
    scan_chunk_kernel<<<gs, 128>>>();
    combine_kernel<<<NB, HID>>>();
    scan_write_kernel<<<gs, 128>>>(out);
}

// round 12
// speedup vs baseline: 5.4311x; 1.1347x over previous
#include <cuda_runtime.h>
#include <cuda_fp16.h>
#include <cstdint>
#include <math.h>

// Problem dims (fixed by the reference)
#define NB 8
#define LSEQ 4096
#define HID 512
#define KDIM 512
#define ODIM 1536              // 3*HID
#define MROWS (NB * LSEQ)      // 32768
#define CHUNK 32
#define NCHUNK (LSEQ / CHUNK)  // 128

// Scratch (allocation-free rule: __device__ globals)
__device__ __half g_preh[(size_t)MROWS * ODIM];    // 96 MB: fp16 preactivations
__device__ float g_P[NCHUNK * NB * HID];           // 2 MB
__device__ float g_Q[NCHUNK * NB * HID];           // 2 MB
__device__ float g_hs[NCHUNK * NB * HID];          // 2 MB
__device__ __half g_xhi[(size_t)MROWS * KDIM];     // 32 MB
__device__ __half g_whi[(size_t)ODIM * KDIM];      // 1.5 MB

// ---------------------------------------------------------------------------
// PTX helpers (baseline sm_80+ only — plain sm_103 target rejects tcgen05)
// ---------------------------------------------------------------------------
__device__ __forceinline__ uint32_t smem_to_u32(const void* p) {
    uint32_t a;
    asm("{ .reg .u64 t; cvta.to.shared.u64 t, %1; cvt.u32.u64 %0, t; }"
        : "=r"(a) : "l"(p));
    return a;
}

#define CP_ASYNC16(s, g) \
    asm volatile("cp.async.cg.shared.global [%0], [%1], 16;" :: "r"(s), "l"(g))
#define CP_COMMIT() asm volatile("cp.async.commit_group;" ::: "memory")
#define CP_WAIT(n)  asm volatile("cp.async.wait_group %0;" :: "n"(n) : "memory")

#define LDMX4(r0, r1, r2, r3, addr) \
    asm volatile("ldmatrix.sync.aligned.m8n8.x4.shared.b16 {%0,%1,%2,%3}, [%4];" \
                 : "=r"(r0), "=r"(r1), "=r"(r2), "=r"(r3) : "r"(addr))

#define MMA16816(d, a0, a1, a2, a3, b0, b1) \
    asm volatile("mma.sync.aligned.m16n8k16.row.col.f32.f16.f16.f32 " \
                 "{%0,%1,%2,%3}, {%4,%5,%6,%7}, {%8,%9}, {%0,%1,%2,%3};" \
                 : "+f"((d)[0]), "+f"((d)[1]), "+f"((d)[2]), "+f"((d)[3]) \
                 : "r"(a0), "r"(a1), "r"(a2), "r"(a3), "r"(b0), "r"(b1))

// ---------------------------------------------------------------------------
// Kernel 0: fp32 -> fp16 conversions
// ---------------------------------------------------------------------------
__global__ __launch_bounds__(256)
void cvt_x_kernel(const float* __restrict__ x) {
    const size_t i0 = ((size_t)blockIdx.x * 256 + threadIdx.x) * 4;
    float4 v = *(const float4*)(x + i0);
    *(__half2*)(g_xhi + i0) = __floats2half2_rn(v.x, v.y);
    *(__half2*)(g_xhi + i0 + 2) = __floats2half2_rn(v.z, v.w);
}

__global__ __launch_bounds__(256)
void cvt_w_kernel(const float* __restrict__ W) {
    const size_t i0 = ((size_t)blockIdx.x * 256 + threadIdx.x) * 4;
    float4 v = *(const float4*)(W + i0);
    *(__half2*)(g_whi + i0) = __floats2half2_rn(v.x, v.y);
    *(__half2*)(g_whi + i0 + 2) = __floats2half2_rn(v.z, v.w);
}

// ---------------------------------------------------------------------------
// Kernel 1: fp16 mma.sync GEMM, single pass, fp16 output.
//   pre[m][o] = x[m][k] * W[o][k] + b[o]
// CTA tile 128x128, 8 warps (warp tile 32x64), BK=64, 3-stage cp.async.
// ---------------------------------------------------------------------------
#define BK 64
#define NKC (KDIM / BK)            // 8 k-chunks
#define TILE_B (128 * BK * 2)      // 16384 bytes per tile
#define STAGE_B (2 * TILE_B)       // 32768 bytes per stage
#define NSTAGE 3
#define SM_GEMM (NSTAGE * STAGE_B) // 98304 bytes

__device__ __forceinline__ void load_stage_g(
    uint32_t sbase, int stage, int kc, int tid,
    const __half* Ah, const __half* Bh) {
    const int k0 = kc * BK;
    const uint32_t st = sbase + stage * STAGE_B;
    const __half* gsrc[2] = {Ah, Bh};
#pragma unroll
    for (int tt = 0; tt < 2; tt++) {
#pragma unroll
        for (int j = 0; j < 4; j++) {
            const int idx = j * 256 + tid;      // 0..1023
            const int row = idx >> 3;           // 0..127
            const int c = idx & 7;              // 16B chunk in 128B row
            const char* g = (const char*)(gsrc[tt] + (size_t)row * KDIM + k0 + c * 8);
            const uint32_t s = st + tt * TILE_B + row * 128 +
                               ((c ^ (row & 7)) * 16);
            CP_ASYNC16(s, g);
        }
    }
}

__global__ __launch_bounds__(256)
void gemm_mma_kernel(const float* __restrict__ bias) {
    extern __shared__ char smem[];
    const uint32_t sbase = smem_to_u32(smem);
    const int tid = threadIdx.x;
    const int lane = tid & 31;
    const int w = tid >> 5;
    const int wm = w & 3;    // 4 M groups of 32 rows
    const int wn = w >> 2;   // 2 N groups of 64 cols
    const int bx = blockIdx.x;  // N tile (0..11)
    const int by = blockIdx.y;  // M tile (0..255)

    const __half* Ah = g_xhi + (size_t)by * 128 * KDIM;
    const __half* Bh = g_whi + (size_t)bx * 128 * KDIM;

    float acc[2][8][4];
#pragma unroll
    for (int mi = 0; mi < 2; mi++)
#pragma unroll
        for (int ni = 0; ni < 8; ni++)
#pragma unroll
            for (int r = 0; r < 4; r++) acc[mi][ni][r] = 0.f;

    const int lrow = lane & 15;
    const int lhalf = lane >> 4;

    load_stage_g(sbase, 0, 0, tid, Ah, Bh); CP_COMMIT();
    load_stage_g(sbase, 1, 1, tid, Ah, Bh); CP_COMMIT();

    for (int kc = 0; kc < NKC; kc++) {
        if (kc == NKC - 1) { CP_WAIT(0); } else { CP_WAIT(1); }
        __syncthreads();
        const int stage = kc % NSTAGE;
        if (kc + 2 < NKC) {
            load_stage_g(sbase, (kc + 2) % NSTAGE, kc + 2, tid, Ah, Bh);
            CP_COMMIT();
        }

        const uint32_t st = sbase + stage * STAGE_B;
#pragma unroll
        for (int s = 0; s < 4; s++) {   // four k16 steps per BK=64
            uint32_t af[2][4], bf[4][4];
#pragma unroll
            for (int mi = 0; mi < 2; mi++) {
                const int row = wm * 32 + mi * 16 + lrow;
                const int cS = (s * 2 + lhalf) ^ (row & 7);
                LDMX4(af[mi][0], af[mi][1], af[mi][2], af[mi][3],
                      st + row * 128 + cS * 16);
            }
#pragma unroll
            for (int nt = 0; nt < 4; nt++) {
                const int row = wn * 64 + nt * 16 + lrow;
                const int cS = (s * 2 + lhalf) ^ (row & 7);
                LDMX4(bf[nt][0], bf[nt][1], bf[nt][2], bf[nt][3],
                      st + TILE_B + row * 128 + cS * 16);
            }
#pragma unroll
            for (int mi = 0; mi < 2; mi++)
#pragma unroll
                for (int nt = 0; nt < 4; nt++)
#pragma unroll
                    for (int a = 0; a < 2; a++) {
                        const int ni = nt * 2 + a;
                        MMA16816(acc[mi][ni], af[mi][0], af[mi][1], af[mi][2],
                                 af[mi][3], bf[nt][a], bf[nt][a + 2]);
                    }
        }
    }

    // Epilogue: add bias, write fp16 pre
#pragma unroll
    for (int mi = 0; mi < 2; mi++) {
        const int row = by * 128 + wm * 32 + mi * 16 + (lane >> 2);
#pragma unroll
        for (int ni = 0; ni < 8; ni++) {
            const int col = bx * 128 + wn * 64 + ni * 8 + (lane & 3) * 2;
            const float b0 = bias[col], b1 = bias[col + 1];
            *(__half2*)(g_preh + (size_t)row * ODIM + col) =
                __floats2half2_rn(acc[mi][ni][0] + b0, acc[mi][ni][1] + b1);
            *(__half2*)(g_preh + (size_t)(row + 8) * ODIM + col) =
                __floats2half2_rn(acc[mi][ni][2] + b0, acc[mi][ni][3] + b1);
        }
    }
}

// ---------------------------------------------------------------------------
// Gate math (closed form):
//   f = (1+e^{-ip}) / (2 + e^{-fp} + e^{-ip});   i = 1 - f
//   g = hp>=0 ? hp+0.5 : sigmoid(hp);  v = i*g
// ---------------------------------------------------------------------------
__device__ __forceinline__ void gates(float fp, float ip, float hp,
                                      float& f, float& v) {
    const float a = __expf(-fp);
    const float b = __expf(-ip);
    f = __fdividef(1.f + b, 2.f + a + b);
    const float ig = 1.f - f;
    const float gg = (hp >= 0.f) ? (hp + 0.5f)
                                 : __fdividef(1.f, 1.f + __expf(-hp));
    v = ig * gg;
}

__device__ __forceinline__ void gates4(const __half* pre, int h4,
                                       float4& f, float4& v) {
    const __half2 fp01 = *(const __half2*)(pre + h4);
    const __half2 fp23 = *(const __half2*)(pre + h4 + 2);
    const __half2 ip01 = *(const __half2*)(pre + HID + h4);
    const __half2 ip23 = *(const __half2*)(pre + HID + h4 + 2);
    const __half2 hp01 = *(const __half2*)(pre + 2 * HID + h4);
    const __half2 hp23 = *(const __half2*)(pre + 2 * HID + h4 + 2);
    const float2 fpa = __half22float2(fp01), fpb = __half22float2(fp23);
    const float2 ipa = __half22float2(ip01), ipb = __half22float2(ip23);
    const float2 hpa = __half22float2(hp01), hpb = __half22float2(hp23);
    gates(fpa.x, ipa.x, hpa.x, f.x, v.x);
    gates(fpa.y, ipa.y, hpa.y, f.y, v.y);
    gates(fpb.x, ipb.x, hpb.x, f.z, v.z);
    gates(fpb.y, ipb.y, hpb.y, f.w, v.w);
}

// ---------------------------------------------------------------------------
// Kernel 2: per-chunk scan (4 h per thread): compute gates from fp16 pre,
// accumulate chunk (P, Q) s.t. h_end = P*h_start + Q. No f/v stored.
// ---------------------------------------------------------------------------
__global__ __launch_bounds__(128)
void scan_chunk_kernel() {
    const int h4 = threadIdx.x * 4;
    const int n = blockIdx.y;
    const int c = blockIdx.x;
    const size_t m0 = (size_t)n * LSEQ + (size_t)c * CHUNK;

    float4 P = make_float4(1.f, 1.f, 1.f, 1.f);
    float4 Q = make_float4(0.f, 0.f, 0.f, 0.f);
#pragma unroll 4
    for (int t = 0; t < CHUNK; t++) {
        const __half* pre = g_preh + (m0 + t) * ODIM;
        float4 f, v;
        gates4(pre, h4, f, v);
        P.x *= f.x; P.y *= f.y; P.z *= f.z; P.w *= f.w;
        Q.x = fmaf(f.x, Q.x, v.x);
        Q.y = fmaf(f.y, Q.y, v.y);
        Q.z = fmaf(f.z, Q.z, v.z);
        Q.w = fmaf(f.w, Q.w, v.w);
    }
    const int idx = c * (NB * HID) + n * HID + h4;
    *(float4*)(g_P + idx) = P;
    *(float4*)(g_Q + idx) = Q;
}

// ---------------------------------------------------------------------------
// Kernel 3: sequential combine over chunks (tiny).
// ---------------------------------------------------------------------------
__global__ __launch_bounds__(HID)
void combine_kernel() {
    const int n = blockIdx.x;
    const int h = threadIdx.x;
    float hc = 1e-6f;  // HX_INIT
    for (int c = 0; c < NCHUNK; c++) {
        const int idx = c * (NB * HID) + n * HID + h;
        g_hs[idx] = hc;
        hc = fmaf(g_P[idx], hc, g_Q[idx]);
    }
}

// ---------------------------------------------------------------------------
// Kernel 4: replay each chunk from its start state (recompute gates from
// fp16 pre — no stored f/v); write fp32 output.
// ---------------------------------------------------------------------------
__global__ __launch_bounds__(128)
void scan_write_kernel(float* __restrict__ out) {
    const int h4 = threadIdx.x * 4;
    const int n = blockIdx.y;
    const int c = blockIdx.x;
    const size_t m0 = (size_t)n * LSEQ + (size_t)c * CHUNK;

    float4 hc = *(const float4*)(g_hs + c * (NB * HID) + n * HID + h4);
#pragma unroll 4
    for (int t = 0; t < CHUNK; t++) {
        const __half* pre = g_preh + (m0 + t) * ODIM;
        float4 f, v;
        gates4(pre, h4, f, v);
        hc.x = fmaf(f.x, hc.x, v.x);
        hc.y = fmaf(f.y, hc.y, v.y);
        hc.z = fmaf(f.z, hc.z, v.z);
        hc.w = fmaf(f.w, hc.w, v.w);
        *(float4*)(out + (m0 + t) * HID + h4) = hc;
    }
}

// ---------------------------------------------------------------------------
extern "C" void kernel_launch(void* const* d_in, const int* in_sizes, int n_in,
                              void* d_out, int out_size) {
    const float* x = (const float*)d_in[0];  // (8, 4096, 512)
    const float* W = (const float*)d_in[1];  // (1536, 512)
    const float* b = (const float*)d_in[2];  // (1536,)
    float* out = (float*)d_out;              // (8, 4096, 512)

    cudaFuncSetAttribute(gemm_mma_kernel,
                         cudaFuncAttributeMaxDynamicSharedMemorySize, SM_GEMM);

    cvt_x_kernel<<<(MROWS * KDIM) / (256 * 4), 256>>>(x);
    cvt_w_kernel<<<(ODIM * KDIM) / (256 * 4), 256>>>(W);

    dim3 gg(ODIM / 128, MROWS / 128);        // (12, 256)
    gemm_mma_kernel<<<gg, 256, SM_GEMM>>>(b);

    dim3 gs(NCHUNK, NB);                     // (128, 8) = 1024 blocks
    scan_chunk_kernel<<<gs, 128>>>();
    combine_kernel<<<NB, HID>>>();
    scan_write_kernel<<<gs, 128>>>(out);
}